// round 9
// baseline (speedup 1.0000x reference)
#include <cuda_runtime.h>

typedef unsigned long long ull;

#define C_DIM 1024
#define TPB   128
#define TILE_R 128
#define PAD  132           // row stride (floats); %4==0 for LDS.128 alignment

// smem arena layout (floats)
#define SM_X  0                         // [128][PAD] RAW x transposed: k 0..63 = ht, 64..127 = kc
#define SM_WD (128*PAD)                 // [64][64]   natural-layout weight tile
#define SM_B1 (SM_WD + 64*64)           // [64][PAD]
#define SM_B2 (SM_B1 + 64*PAD)
#define SM_B3 (SM_B2 + 64*PAD)
#define SM_TOT (SM_B3 + 64*PAD)         // 46336 floats = 185344 B

__device__ float g_adj[2 * C_DIM];

__device__ __forceinline__ float4 ldg4(const float* p) {
    return __ldg(reinterpret_cast<const float4*>(p));
}
__device__ __forceinline__ float clipf(float v, float lo, float hi) {
    return fminf(fmaxf(v, lo), hi);
}
__device__ __forceinline__ float sigm(float x) { return 1.f / (1.f + expf(-x)); }

__device__ __forceinline__ void ffma2(ull& d, ull a, ull b) {
    asm("fma.rn.f32x2 %0, %1, %2, %0;" : "+l"(d) : "l"(a), "l"(b));
}
__device__ __forceinline__ ull pk(float x, float y) {
    ull v; asm("mov.b64 %0, {%1, %2};" : "=l"(v) : "f"(x), "f"(y)); return v;
}
__device__ __forceinline__ float2 upk(ull v) {
    float2 r; asm("mov.b64 {%0, %1}, %2;" : "=f"(r.x), "=f"(r.y) : "l"(v)); return r;
}

// thread tile: rows ty*8..ty*8+7 x outputs o = 4tx+32g+2p (+1), acc[r*4+g*2+p]

// ---------------------------------------------------------------------------
// adj pre-kernel
// ---------------------------------------------------------------------------
__global__ void gkt_adj(const int* __restrict__ qt, const float* __restrict__ onehot,
                        const float* __restrict__ graphs) {
    __shared__ int nz[C_DIM];
    __shared__ int wcnt[32];
    __shared__ int woff[33];
    const int t = threadIdx.x, wid = t >> 5, lane = t & 31;
    const int q0 = qt[0];
    const bool on = (onehot[(long)q0 * C_DIM + t] > 0.5f);
    unsigned bal = __ballot_sync(0xffffffffu, on);
    if (lane == 0) wcnt[wid] = __popc(bal);
    __syncthreads();
    if (t == 0) { int s = 0; for (int w = 0; w < 32; ++w) { woff[w] = s; s += wcnt[w]; } woff[32] = s; }
    __syncthreads();
    if (on) nz[woff[wid] + __popc(bal & ((1u << lane) - 1u))] = t;
    __syncthreads();
    const int n = woff[32];
    const float denom = fmaxf((float)n, 1.f);
#pragma unroll
    for (int k = 0; k < 2; ++k) {
        float s = 0.f;
        for (int idx = 0; idx < n; ++idx)
            s += graphs[k * C_DIM * C_DIM + nz[idx] * C_DIM + t];
        g_adj[k * C_DIM + t] = clipf(s / denom, -5.f, 5.f);
    }
}

// ---------------------------------------------------------------------------
// helpers
// ---------------------------------------------------------------------------

// Stage a 64x64 weight tile into WD, natural layout (row = 64 floats).
__device__ __forceinline__ void stage_w(float* __restrict__ WD, const float* __restrict__ src,
                                        int rstride, int t) {
#pragma unroll
    for (int i = t; i < 64 * 16; i += TPB) {
        int kk = i >> 4, o4 = i & 15;
        *reinterpret_cast<float4*>(WD + kk * 64 + o4 * 4) = ldg4(src + kk * rstride + o4 * 4);
    }
}

// acc += A(8 rows) x W(8 outs): per k-step 2 LDS.128 (rows) + 2 LDS.128 (weights) + 32 FFMA2.
template<bool CLIP>
__device__ __forceinline__ void gemm8(const float* __restrict__ A, const float* __restrict__ WD,
                                      int ty, int tx, ull acc[32]) {
    const float* Ab = A + ty * 8;
    const ulonglong2* Wb = reinterpret_cast<const ulonglong2*>(WD) + tx;   // row = 16 u2
#pragma unroll 8
    for (int kk = 0; kk < 64; ++kk) {
        float4 a0 = *reinterpret_cast<const float4*>(Ab + kk * PAD);
        float4 a1 = *reinterpret_cast<const float4*>(Ab + kk * PAD + 4);
        if (CLIP) {
            a0.x = clipf(a0.x, -5.f, 5.f); a0.y = clipf(a0.y, -5.f, 5.f);
            a0.z = clipf(a0.z, -5.f, 5.f); a0.w = clipf(a0.w, -5.f, 5.f);
            a1.x = clipf(a1.x, -5.f, 5.f); a1.y = clipf(a1.y, -5.f, 5.f);
            a1.z = clipf(a1.z, -5.f, 5.f); a1.w = clipf(a1.w, -5.f, 5.f);
        }
        ull ad[8] = { pk(a0.x, a0.x), pk(a0.y, a0.y), pk(a0.z, a0.z), pk(a0.w, a0.w),
                      pk(a1.x, a1.x), pk(a1.y, a1.y), pk(a1.z, a1.z), pk(a1.w, a1.w) };
        ulonglong2 w0 = Wb[kk * 16];        // floats 4tx .. 4tx+3
        ulonglong2 w1 = Wb[kk * 16 + 8];    // floats 32+4tx .. 32+4tx+3
#pragma unroll
        for (int r = 0; r < 8; ++r) {
            ffma2(acc[r * 4 + 0], ad[r], w0.x);
            ffma2(acc[r * 4 + 1], ad[r], w0.y);
            ffma2(acc[r * 4 + 2], ad[r], w1.x);
            ffma2(acc[r * 4 + 3], ad[r], w1.y);
        }
    }
}

__device__ __forceinline__ void init_bias(ull acc[32], const float* __restrict__ b1p,
                                          const float* __restrict__ b2p, int tx) {
#pragma unroll
    for (int g = 0; g < 2; ++g)
#pragma unroll
    for (int p = 0; p < 2; ++p) {
        int o = 4 * tx + 32 * g + 2 * p;
        float vx = __ldg(b1p + o), vy = __ldg(b1p + o + 1);
        if (b2p) { vx += __ldg(b2p + o); vy += __ldg(b2p + o + 1); }
        ull pv = pk(vx, vy);
#pragma unroll
        for (int r = 0; r < 8; ++r) acc[r * 4 + g * 2 + p] = pv;
    }
}

// ---------------------------------------------------------------------------
// fused main kernel
// ---------------------------------------------------------------------------
__global__ __launch_bounds__(TPB, 1) void gkt_main(
    const int*   __restrict__ qt,     const float* __restrict__ ht,
    const float* __restrict__ onehot, const float* __restrict__ kc,
    const float* __restrict__ nw_ptr,
    const float* __restrict__ Ws1, const float* __restrict__ bs1,
    const float* __restrict__ Ws2, const float* __restrict__ bs2,
    const float* __restrict__ Wn1, const float* __restrict__ bn1,
    const float* __restrict__ Wn2, const float* __restrict__ bn2,
    const float* __restrict__ ea_w,
    const float* __restrict__ We,  const float* __restrict__ be,
    const float* __restrict__ Wa,  const float* __restrict__ ba,
    const float* __restrict__ W_ih, const float* __restrict__ b_ih,
    const float* __restrict__ W_hh, const float* __restrict__ b_hh,
    const float* __restrict__ Wp,  const float* __restrict__ bp,
    float* __restrict__ out)
{
    extern __shared__ float sm[];
    float* X  = sm + SM_X;              // raw [ht | kc], transposed
    float* XH = sm + SM_X;              // alias: k rows 0..63 = raw ht
    float* WD = sm + SM_WD;
    float* B1 = sm + SM_B1;
    float* B2 = sm + SM_B2;
    float* B3 = sm + SM_B3;
    float* B4 = sm + SM_X + 64 * PAD;   // kc region, reused after fix-up
    float* tmp = WD;                    // fix-up scratch
    int*   mlist = (int*)(WD + 64);
    int*   mcnt  = (int*)(WD + 192);

    const int t  = threadIdx.x;
    const int tx = t & 7, ty = t >> 3;        // rows = ty*8 .. ty*8+7
    const int row0 = blockIdx.x * TILE_R;
    const int b  = row0 >> 10;
    const int c0 = row0 & (C_DIM - 1);
    const int q  = __ldg(&qt[b]);

    // ---- stage X transposed, RAW ----
#pragma unroll
    for (int i = t; i < TILE_R * 64; i += TPB) {
        int row = i >> 6, k = i & 63;
        X[k * PAD + row]        = ht[(row0 + row) * 64 + k];
        X[(64 + k) * PAD + row] = kc[(c0 + row) * 64 + k];
    }

    ull acc[32];
    const float wcl = clipf(__ldg(nw_ptr), 0.1f, 0.9f);

    // ================= stage 1: H1(k=0) = relu(clip(X) @ Wn1[0][128:256]) ==
    init_bias(acc, bn1, nullptr, tx);
    __syncthreads();
    stage_w(WD, Wn1 + (0 * 256 + 128) * 64, 64, t);
    __syncthreads();
    gemm8<true>(X, WD, ty, tx, acc);
    __syncthreads();
    stage_w(WD, Wn1 + (0 * 256 + 192) * 64, 64, t);
    __syncthreads();
    gemm8<true>(X + 64 * PAD, WD, ty, tx, acc);
#pragma unroll
    for (int r = 0; r < 8; ++r) {
        int row = ty * 8 + r;
#pragma unroll
        for (int g = 0; g < 2; ++g)
#pragma unroll
        for (int p = 0; p < 2; ++p) {
            int o = 4 * tx + 32 * g + 2 * p;
            float2 v = upk(acc[r * 4 + g * 2 + p]);
            B1[o * PAD + row]       = fmaxf(v.x, 0.f);
            B1[(o + 1) * PAD + row] = fmaxf(v.y, 0.f);
        }
    }

    // ================= stage 2: nf0 = clip5(aj0 * clip5(relu(H1 @ Wn2[0]))) =
    init_bias(acc, bn2, nullptr, tx);
    __syncthreads();
    stage_w(WD, Wn2, 64, t);
    __syncthreads();
    gemm8<false>(B1, WD, ty, tx, acc);
#pragma unroll
    for (int r = 0; r < 8; ++r) {
        int row = ty * 8 + r;
        float a0 = __ldg(&g_adj[c0 + row]);
#pragma unroll
        for (int g = 0; g < 2; ++g)
#pragma unroll
        for (int p = 0; p < 2; ++p) {
            int o = 4 * tx + 32 * g + 2 * p;
            float2 v = upk(acc[r * 4 + g * 2 + p]);
            float nb0x = fminf(fmaxf(v.x, 0.f), 5.f);
            float nb0y = fminf(fmaxf(v.y, 0.f), 5.f);
            B2[o * PAD + row]       = clipf(a0 * nb0x, -5.f, 5.f);
            B2[(o + 1) * PAD + row] = clipf(a0 * nb0y, -5.f, 5.f);
        }
    }

    // ================= stage 3: H1(k=1) ====================================
    init_bias(acc, bn1 + 64, nullptr, tx);
    __syncthreads();
    stage_w(WD, Wn1 + (1 * 256 + 128) * 64, 64, t);
    __syncthreads();
    gemm8<true>(X, WD, ty, tx, acc);
    __syncthreads();
    stage_w(WD, Wn1 + (1 * 256 + 192) * 64, 64, t);
    __syncthreads();
    gemm8<true>(X + 64 * PAD, WD, ty, tx, acc);
#pragma unroll
    for (int r = 0; r < 8; ++r) {
        int row = ty * 8 + r;
#pragma unroll
        for (int g = 0; g < 2; ++g)
#pragma unroll
        for (int p = 0; p < 2; ++p) {
            int o = 4 * tx + 32 * g + 2 * p;
            float2 v = upk(acc[r * 4 + g * 2 + p]);
            B1[o * PAD + row]       = fmaxf(v.x, 0.f);
            B1[(o + 1) * PAD + row] = fmaxf(v.y, 0.f);
        }
    }

    // ================= stage 4: nf = clip5(w*nf0 + (1-w)*aj1*nb1) ==========
    init_bias(acc, bn2 + 64, nullptr, tx);
    __syncthreads();
    stage_w(WD, Wn2 + 64 * 64, 64, t);
    __syncthreads();
    gemm8<false>(B1, WD, ty, tx, acc);
#pragma unroll
    for (int r = 0; r < 8; ++r) {
        int row = ty * 8 + r;
        float a1 = __ldg(&g_adj[C_DIM + c0 + row]);
#pragma unroll
        for (int g = 0; g < 2; ++g)
#pragma unroll
        for (int p = 0; p < 2; ++p) {
            int o = 4 * tx + 32 * g + 2 * p;
            float2 v = upk(acc[r * 4 + g * 2 + p]);
            float nb1x = fminf(fmaxf(v.x, 0.f), 5.f);
            float nb1y = fminf(fmaxf(v.y, 0.f), 5.f);
            float nf0x = B2[o * PAD + row];
            float nf0y = B2[(o + 1) * PAD + row];
            B2[o * PAD + row]       = clipf(wcl * nf0x + (1.f - wcl) * a1 * nb1x, -5.f, 5.f);
            B2[(o + 1) * PAD + row] = clipf(wcl * nf0y + (1.f - wcl) * a1 * nb1y, -5.f, 5.f);
        }
    }

    // ================= stage 5: masked-row self-MLP fix-up ==================
    __syncthreads();
    if (t == 0) *mcnt = 0;
    __syncthreads();
    if (t < TILE_R) {
        float m = __ldg(&onehot[(long)q * C_DIM + c0 + t]);
        if (m > 0.5f) { int pos = atomicAdd(mcnt, 1); mlist[pos] = t; }
    }
    __syncthreads();
    const int nm = *mcnt;
    for (int idx = 0; idx < nm; ++idx) {
        int row = mlist[idx];
        if (t < 64) {
            float a = __ldg(bs1 + t);
            for (int k = 0; k < 128; ++k) a += X[k * PAD + row] * __ldg(Ws1 + k * 64 + t);
            tmp[t] = fmaxf(a, 0.f);
        }
        __syncthreads();
        if (t < 64) {
            float a = __ldg(bs2 + t);
            for (int k = 0; k < 64; ++k) a += tmp[k] * __ldg(Ws2 + k * 64 + t);
            B2[t * PAD + row] = clipf(fmaxf(a, 0.f), -10.f, 10.f);
        }
        __syncthreads();
    }
    // B2 now holds m_next (mn)

    // ================= stage 6: sigE = sigmoid(mn @ We + be) -> B1 =========
    init_bias(acc, be, nullptr, tx);
    __syncthreads();
    stage_w(WD, We, 64, t);
    __syncthreads();
    gemm8<false>(B2, WD, ty, tx, acc);
#pragma unroll
    for (int r = 0; r < 8; ++r) {
        int row = ty * 8 + r;
#pragma unroll
        for (int g = 0; g < 2; ++g)
#pragma unroll
        for (int p = 0; p < 2; ++p) {
            int o = 4 * tx + 32 * g + 2 * p;
            float2 v = upk(acc[r * 4 + g * 2 + p]);
            B1[o * PAD + row]       = sigm(v.x);
            B1[(o + 1) * PAD + row] = sigm(v.y);
        }
    }

    // ================= stage 7: res = mn - g*sigE*mn + g*tanh(mn@Wa+ba) -> B3
    init_bias(acc, ba, nullptr, tx);
    __syncthreads();
    stage_w(WD, Wa, 64, t);
    __syncthreads();
    gemm8<false>(B2, WD, ty, tx, acc);
#pragma unroll
    for (int r = 0; r < 8; ++r) {
        int row = ty * 8 + r;
        float gg = __ldg(&ea_w[c0 + row]);
#pragma unroll
        for (int g = 0; g < 2; ++g)
#pragma unroll
        for (int p = 0; p < 2; ++p) {
            int o = 4 * tx + 32 * g + 2 * p;
            float2 v = upk(acc[r * 4 + g * 2 + p]);
            float mnx = B2[o * PAD + row],       sgx = B1[o * PAD + row];
            float mny = B2[(o + 1) * PAD + row], sgy = B1[(o + 1) * PAD + row];
            B3[o * PAD + row]       = mnx - gg * sgx * mnx + gg * tanhf(v.x);
            B3[(o + 1) * PAD + row] = mny - gg * sgy * mny + gg * tanhf(v.y);
        }
    }

    // ================= stage 8: r gate -> B1 ================================
    init_bias(acc, b_ih, b_hh, tx);
    __syncthreads();
    stage_w(WD, W_ih, 192, t);
    __syncthreads();
    gemm8<false>(B3, WD, ty, tx, acc);
    __syncthreads();
    stage_w(WD, W_hh, 192, t);
    __syncthreads();
    gemm8<false>(XH, WD, ty, tx, acc);
#pragma unroll
    for (int r = 0; r < 8; ++r) {
        int row = ty * 8 + r;
#pragma unroll
        for (int g = 0; g < 2; ++g)
#pragma unroll
        for (int p = 0; p < 2; ++p) {
            int o = 4 * tx + 32 * g + 2 * p;
            float2 v = upk(acc[r * 4 + g * 2 + p]);
            B1[o * PAD + row]       = sigm(v.x);
            B1[(o + 1) * PAD + row] = sigm(v.y);
        }
    }

    // ================= stage 9: z gate -> B2 (mn dead) ======================
    init_bias(acc, b_ih + 64, b_hh + 64, tx);
    __syncthreads();
    stage_w(WD, W_ih + 64, 192, t);
    __syncthreads();
    gemm8<false>(B3, WD, ty, tx, acc);
    __syncthreads();
    stage_w(WD, W_hh + 64, 192, t);
    __syncthreads();
    gemm8<false>(XH, WD, ty, tx, acc);
#pragma unroll
    for (int r = 0; r < 8; ++r) {
        int row = ty * 8 + r;
#pragma unroll
        for (int g = 0; g < 2; ++g)
#pragma unroll
        for (int p = 0; p < 2; ++p) {
            int o = 4 * tx + 32 * g + 2 * p;
            float2 v = upk(acc[r * 4 + g * 2 + p]);
            B2[o * PAD + row]       = sigm(v.x);
            B2[(o + 1) * PAD + row] = sigm(v.y);
        }
    }

    // ================= stage 10a: hn = ht@Whhn + bhhn -> B4 (kc region) ====
    init_bias(acc, b_hh + 128, nullptr, tx);
    __syncthreads();
    stage_w(WD, W_hh + 128, 192, t);
    __syncthreads();
    gemm8<false>(XH, WD, ty, tx, acc);
    __syncthreads();          // ensure no one still reads kc region (fix-up done long ago; safe)
#pragma unroll
    for (int r = 0; r < 8; ++r) {
        int row = ty * 8 + r;
#pragma unroll
        for (int g = 0; g < 2; ++g)
#pragma unroll
        for (int p = 0; p < 2; ++p) {
            int o = 4 * tx + 32 * g + 2 * p;
            float2 v = upk(acc[r * 4 + g * 2 + p]);
            B4[o * PAD + row]       = v.x;
            B4[(o + 1) * PAD + row] = v.y;
        }
    }

    // ================= stage 10b: n, h_next -> B1 ==========================
    init_bias(acc, b_ih + 128, nullptr, tx);
    __syncthreads();
    stage_w(WD, W_ih + 128, 192, t);
    __syncthreads();
    gemm8<false>(B3, WD, ty, tx, acc);
#pragma unroll
    for (int r = 0; r < 8; ++r) {
        int row = ty * 8 + r;
#pragma unroll
        for (int g = 0; g < 2; ++g)
#pragma unroll
        for (int p = 0; p < 2; ++p) {
            int o = 4 * tx + 32 * g + 2 * p;
            float2 v = upk(acc[r * 4 + g * 2 + p]);
            float hnx = B4[o * PAD + row],       hny = B4[(o + 1) * PAD + row];
            float rrx = B1[o * PAD + row],       rry = B1[(o + 1) * PAD + row];
            float zzx = B2[o * PAD + row],       zzy = B2[(o + 1) * PAD + row];
            float hvx = XH[o * PAD + row],       hvy = XH[(o + 1) * PAD + row];
            float nx = tanhf(v.x + rrx * hnx);
            float ny = tanhf(v.y + rry * hny);
            B1[o * PAD + row]       = (1.f - zzx) * nx + zzx * hvx;
            B1[(o + 1) * PAD + row] = (1.f - zzy) * ny + zzy * hvy;
        }
    }

    // ================= stage 11: y = sigm(h_next @ Wp + bp) ================
    __syncthreads();
    {
        float s = __ldg(bp);
#pragma unroll 16
        for (int o = 0; o < 64; ++o)
            s += B1[o * PAD + t] * __ldg(Wp + o);
        out[row0 + t] = sigm(s);
    }
}

extern "C" void kernel_launch(void* const* d_in, const int* in_sizes, int n_in,
                              void* d_out, int out_size) {
    const int*   qt     = (const int*)  d_in[1];
    const float* ht     = (const float*)d_in[2];
    const float* onehot = (const float*)d_in[3];
    const float* kc     = (const float*)d_in[4];
    const float* graphs = (const float*)d_in[5];
    const float* nw     = (const float*)d_in[6];
    const float* Ws1    = (const float*)d_in[7];
    const float* bs1    = (const float*)d_in[8];
    const float* Ws2    = (const float*)d_in[9];
    const float* bs2    = (const float*)d_in[10];
    const float* Wn1    = (const float*)d_in[11];
    const float* bn1    = (const float*)d_in[12];
    const float* Wn2    = (const float*)d_in[13];
    const float* bn2    = (const float*)d_in[14];
    const float* ea_w   = (const float*)d_in[15];
    const float* We     = (const float*)d_in[16];
    const float* be     = (const float*)d_in[17];
    const float* Wa     = (const float*)d_in[18];
    const float* ba     = (const float*)d_in[19];
    const float* W_ih   = (const float*)d_in[20];
    const float* b_ih   = (const float*)d_in[21];
    const float* W_hh   = (const float*)d_in[22];
    const float* b_hh   = (const float*)d_in[23];
    const float* Wp     = (const float*)d_in[24];
    const float* bp     = (const float*)d_in[25];
    float* out = (float*)d_out;

    gkt_adj<<<1, 1024>>>(qt, onehot, graphs);

    const int smem_bytes = SM_TOT * (int)sizeof(float);   // 185344 B
    cudaFuncSetAttribute(gkt_main, cudaFuncAttributeMaxDynamicSharedMemorySize, smem_bytes);
    const int nrows = 256 * C_DIM;
    gkt_main<<<nrows / TILE_R, TPB, smem_bytes>>>(
        qt, ht, onehot, kc, nw,
        Ws1, bs1, Ws2, bs2, Wn1, bn1, Wn2, bn2,
        ea_w, We, be, Wa, ba, W_ih, b_ih, W_hh, b_hh, Wp, bp,
        out);
}

// round 12
// speedup vs baseline: 1.4206x; 1.4206x over previous
#include <cuda_runtime.h>

typedef unsigned long long ull;

#define C_DIM 1024
#define TPB   256
#define TILE_R 128
#define PAD  132           // row stride (floats); %4==0 for LDS.128 alignment

// smem arena layout (floats)
#define SM_X   0                        // [128][PAD] RAW x transposed: k 0..63 = ht, 64..127 = kc
#define SM_WD0 (128*PAD)                // [64][64] weight tile, buffer 0
#define SM_WD1 (SM_WD0 + 4096)         // [64][64] weight tile, buffer 1
#define SM_B1  (SM_WD1 + 4096)
#define SM_B2  (SM_B1 + 64*PAD)
#define SM_B3  (SM_B2 + 64*PAD)
#define SM_TOT (SM_B3 + 64*PAD)         // 50432 floats = 201728 B

__device__ float g_adj[2 * C_DIM];

__device__ __forceinline__ float4 ldg4(const float* p) {
    return __ldg(reinterpret_cast<const float4*>(p));
}
__device__ __forceinline__ float clipf(float v, float lo, float hi) {
    return fminf(fmaxf(v, lo), hi);
}
__device__ __forceinline__ float sigm(float x) { return 1.f / (1.f + expf(-x)); }

__device__ __forceinline__ void ffma2(ull& d, ull a, ull b) {
    asm("fma.rn.f32x2 %0, %1, %2, %0;" : "+l"(d) : "l"(a), "l"(b));
}
__device__ __forceinline__ ull pk(float x, float y) {
    ull v; asm("mov.b64 %0, {%1, %2};" : "=l"(v) : "f"(x), "f"(y)); return v;
}
__device__ __forceinline__ float2 upk(ull v) {
    float2 r; asm("mov.b64 {%0, %1}, %2;" : "=f"(r.x), "=f"(r.y) : "l"(v)); return r;
}

// ---------------------------------------------------------------------------
// adj pre-kernel
// ---------------------------------------------------------------------------
__global__ void gkt_adj(const int* __restrict__ qt, const float* __restrict__ onehot,
                        const float* __restrict__ graphs) {
    __shared__ int nz[C_DIM];
    __shared__ int wcnt[32];
    __shared__ int woff[33];
    const int t = threadIdx.x, wid = t >> 5, lane = t & 31;
    const int q0 = qt[0];
    const bool on = (onehot[(long)q0 * C_DIM + t] > 0.5f);
    unsigned bal = __ballot_sync(0xffffffffu, on);
    if (lane == 0) wcnt[wid] = __popc(bal);
    __syncthreads();
    if (t == 0) { int s = 0; for (int w = 0; w < 32; ++w) { woff[w] = s; s += wcnt[w]; } woff[32] = s; }
    __syncthreads();
    if (on) nz[woff[wid] + __popc(bal & ((1u << lane) - 1u))] = t;
    __syncthreads();
    const int n = woff[32];
    const float denom = fmaxf((float)n, 1.f);
#pragma unroll
    for (int k = 0; k < 2; ++k) {
        float s = 0.f;
        for (int idx = 0; idx < n; ++idx)
            s += graphs[k * C_DIM * C_DIM + nz[idx] * C_DIM + t];
        g_adj[k * C_DIM + t] = clipf(s / denom, -5.f, 5.f);
    }
}

// ---------------------------------------------------------------------------
// weight prefetch pipeline: LDG into regs early, STS after the gemm
// ---------------------------------------------------------------------------
__device__ __forceinline__ void pref_w(float4 pf[4], const float* __restrict__ src,
                                       int rstride, int t) {
#pragma unroll
    for (int i = 0; i < 4; ++i) {
        int idx = t + i * TPB;                  // 0..1023 float4 slots
        int kk = idx >> 4, o4 = idx & 15;
        pf[i] = ldg4(src + kk * rstride + o4 * 4);
    }
}
__device__ __forceinline__ void commit_w(float* __restrict__ WD, const float4 pf[4], int t) {
#pragma unroll
    for (int i = 0; i < 4; ++i) {
        int idx = t + i * TPB;
        *reinterpret_cast<float4*>(WD + idx * 4) = pf[i];
    }
}

// acc += A(4 rows) x W(8 outs): per k-step 1 LDS.128 (rows) + 2 LDS.128 (weights) + 16 FFMA2.
template<bool CLIP>
__device__ __forceinline__ void gemm4(const float* __restrict__ A, const float* __restrict__ WD,
                                      int ty, int tx, ull acc[16]) {
    const float* Ab = A + ty * 4;
    const ulonglong2* Wb = reinterpret_cast<const ulonglong2*>(WD) + tx;   // row = 16 u2
#pragma unroll 4
    for (int kk = 0; kk < 64; ++kk) {
        float4 av = *reinterpret_cast<const float4*>(Ab + kk * PAD);
        if (CLIP) {
            av.x = clipf(av.x, -5.f, 5.f); av.y = clipf(av.y, -5.f, 5.f);
            av.z = clipf(av.z, -5.f, 5.f); av.w = clipf(av.w, -5.f, 5.f);
        }
        ull ad[4] = { pk(av.x, av.x), pk(av.y, av.y), pk(av.z, av.z), pk(av.w, av.w) };
        ulonglong2 w0 = Wb[kk * 16];        // floats 4tx .. 4tx+3
        ulonglong2 w1 = Wb[kk * 16 + 8];    // floats 32+4tx .. 32+4tx+3
#pragma unroll
        for (int r = 0; r < 4; ++r) {
            ffma2(acc[r * 4 + 0], ad[r], w0.x);
            ffma2(acc[r * 4 + 1], ad[r], w0.y);
            ffma2(acc[r * 4 + 2], ad[r], w1.x);
            ffma2(acc[r * 4 + 3], ad[r], w1.y);
        }
    }
}

__device__ __forceinline__ void init_bias(ull acc[16], const float* __restrict__ b1p,
                                          const float* __restrict__ b2p, int tx) {
#pragma unroll
    for (int g = 0; g < 2; ++g)
#pragma unroll
    for (int p = 0; p < 2; ++p) {
        int o = 4 * tx + 32 * g + 2 * p;
        float vx = __ldg(b1p + o), vy = __ldg(b1p + o + 1);
        if (b2p) { vx += __ldg(b2p + o); vy += __ldg(b2p + o + 1); }
        ull pv = pk(vx, vy);
        acc[g * 2 + p] = pv; acc[4 + g * 2 + p] = pv;
        acc[8 + g * 2 + p] = pv; acc[12 + g * 2 + p] = pv;
    }
}

// variadic so commas inside the body survive preprocessing
#define EPI_LOOP(...)                                                          \
    _Pragma("unroll")                                                          \
    for (int r = 0; r < 4; ++r) {                                              \
        int row = ty * 4 + r;                                                  \
        _Pragma("unroll")                                                      \
        for (int g = 0; g < 2; ++g)                                            \
        _Pragma("unroll")                                                      \
        for (int p = 0; p < 2; ++p) {                                          \
            int o = 4 * tx + 32 * g + 2 * p;                                   \
            float2 v = upk(acc[r * 4 + g * 2 + p]);                            \
            __VA_ARGS__                                                        \
        }                                                                      \
    }

// ---------------------------------------------------------------------------
// fused main kernel
// ---------------------------------------------------------------------------
__global__ __launch_bounds__(TPB, 1) void gkt_main(
    const int*   __restrict__ qt,     const float* __restrict__ ht,
    const float* __restrict__ onehot, const float* __restrict__ kc,
    const float* __restrict__ nw_ptr,
    const float* __restrict__ Ws1, const float* __restrict__ bs1,
    const float* __restrict__ Ws2, const float* __restrict__ bs2,
    const float* __restrict__ Wn1, const float* __restrict__ bn1,
    const float* __restrict__ Wn2, const float* __restrict__ bn2,
    const float* __restrict__ ea_w,
    const float* __restrict__ We,  const float* __restrict__ be,
    const float* __restrict__ Wa,  const float* __restrict__ ba,
    const float* __restrict__ W_ih, const float* __restrict__ b_ih,
    const float* __restrict__ W_hh, const float* __restrict__ b_hh,
    const float* __restrict__ Wp,  const float* __restrict__ bp,
    float* __restrict__ out)
{
    extern __shared__ float sm[];
    float* X   = sm + SM_X;             // raw [ht | kc], transposed
    float* XH  = sm + SM_X;             // alias: k rows 0..63 = raw ht
    float* WD0 = sm + SM_WD0;
    float* WD1 = sm + SM_WD1;
    float* B1  = sm + SM_B1;
    float* B2  = sm + SM_B2;
    float* B3  = sm + SM_B3;
    float* B4  = sm + SM_X + 64 * PAD;  // kc region, dead after fix-up
    float* tmp = B3;                    // fix-up scratch (B3 unused until u7)
    int*   mlist = (int*)(B3 + 64);
    int*   mcnt  = (int*)(B3 + 192);

    const int t  = threadIdx.x;
    const int tx = t & 7, ty = t >> 3;        // rows = ty*4 .. ty*4+3
    const int row0 = blockIdx.x * TILE_R;
    const int b  = row0 >> 10;
    const int c0 = row0 & (C_DIM - 1);
    const int q  = __ldg(&qt[b]);

    float4 pf[4];
    ull acc[16];
    const float wcl = clipf(__ldg(nw_ptr), 0.1f, 0.9f);

    // ---- prologue: prefetch tile0, stage raw X, commit tile0 ----
    pref_w(pf, Wn1 + 128 * 64, 64, t);
#pragma unroll
    for (int i = t; i < TILE_R * 64; i += TPB) {
        int row = i >> 6, k = i & 63;
        X[k * PAD + row]        = ht[(row0 + row) * 64 + k];
        X[(64 + k) * PAD + row] = kc[(c0 + row) * 64 + k];
    }
    commit_w(WD0, pf, t);
    __syncthreads();

    // ===== u0: X_lo @ Wn1[0]_lo  (prefetch t1) =====
    init_bias(acc, bn1, nullptr, tx);
    pref_w(pf, Wn1 + 192 * 64, 64, t);
    gemm4<true>(X, WD0, ty, tx, acc);
    commit_w(WD1, pf, t);
    __syncthreads();

    // ===== u1: X_hi @ Wn1[0]_hi -> B1 relu  (prefetch t2 = Wn2[0]) =====
    pref_w(pf, Wn2, 64, t);
    gemm4<true>(X + 64 * PAD, WD1, ty, tx, acc);
    EPI_LOOP(
        B1[o * PAD + row]       = fmaxf(v.x, 0.f);
        B1[(o + 1) * PAD + row] = fmaxf(v.y, 0.f);
    )
    commit_w(WD0, pf, t);
    __syncthreads();

    // ===== u2: B1 @ Wn2[0] -> B2 = nf0  (prefetch t3) =====
    init_bias(acc, bn2, nullptr, tx);
    pref_w(pf, Wn1 + 256 * 64 + 128 * 64, 64, t);
    gemm4<false>(B1, WD0, ty, tx, acc);
    EPI_LOOP(
        float a0 = __ldg(&g_adj[c0 + row]);
        float nb0x = fminf(fmaxf(v.x, 0.f), 5.f);
        float nb0y = fminf(fmaxf(v.y, 0.f), 5.f);
        B2[o * PAD + row]       = clipf(a0 * nb0x, -5.f, 5.f);
        B2[(o + 1) * PAD + row] = clipf(a0 * nb0y, -5.f, 5.f);
    )
    commit_w(WD1, pf, t);
    __syncthreads();

    // ===== u3: X_lo @ Wn1[1]_lo  (prefetch t4) =====
    init_bias(acc, bn1 + 64, nullptr, tx);
    pref_w(pf, Wn1 + 256 * 64 + 192 * 64, 64, t);
    gemm4<true>(X, WD1, ty, tx, acc);
    commit_w(WD0, pf, t);
    __syncthreads();

    // ===== u4: X_hi @ Wn1[1]_hi -> B1 relu  (prefetch t5 = Wn2[1]) =====
    pref_w(pf, Wn2 + 64 * 64, 64, t);
    gemm4<true>(X + 64 * PAD, WD0, ty, tx, acc);
    EPI_LOOP(
        B1[o * PAD + row]       = fmaxf(v.x, 0.f);
        B1[(o + 1) * PAD + row] = fmaxf(v.y, 0.f);
    )
    commit_w(WD1, pf, t);
    __syncthreads();

    // ===== u5: B1 @ Wn2[1] -> B2 = nf  (prefetch t6 = We) =====
    init_bias(acc, bn2 + 64, nullptr, tx);
    pref_w(pf, We, 64, t);
    gemm4<false>(B1, WD1, ty, tx, acc);
    EPI_LOOP(
        float a1 = __ldg(&g_adj[C_DIM + c0 + row]);
        float nb1x = fminf(fmaxf(v.x, 0.f), 5.f);
        float nb1y = fminf(fmaxf(v.y, 0.f), 5.f);
        float nf0x = B2[o * PAD + row];
        float nf0y = B2[(o + 1) * PAD + row];
        B2[o * PAD + row]       = clipf(wcl * nf0x + (1.f - wcl) * a1 * nb1x, -5.f, 5.f);
        B2[(o + 1) * PAD + row] = clipf(wcl * nf0y + (1.f - wcl) * a1 * nb1y, -5.f, 5.f);
    )
    commit_w(WD0, pf, t);
    __syncthreads();

    // ===== masked-row self-MLP fix-up (scratch in B3; WD holds live tile) ===
    if (t == 0) *mcnt = 0;
    __syncthreads();
    if (t < TILE_R) {
        float m = __ldg(&onehot[(long)q * C_DIM + c0 + t]);
        if (m > 0.5f) { int pos = atomicAdd(mcnt, 1); mlist[pos] = t; }
    }
    __syncthreads();
    const int nm = *mcnt;
    for (int idx = 0; idx < nm; ++idx) {
        int row = mlist[idx];
        if (t < 64) {
            float a = __ldg(bs1 + t);
            for (int k = 0; k < 128; ++k) a += X[k * PAD + row] * __ldg(Ws1 + k * 64 + t);
            tmp[t] = fmaxf(a, 0.f);
        }
        __syncthreads();
        if (t < 64) {
            float a = __ldg(bs2 + t);
            for (int k = 0; k < 64; ++k) a += tmp[k] * __ldg(Ws2 + k * 64 + t);
            B2[t * PAD + row] = clipf(fmaxf(a, 0.f), -10.f, 10.f);
        }
        __syncthreads();
    }
    // B2 = m_next (mn)

    // ===== u6: B2 @ We -> B1 = sigE  (prefetch t7 = Wa) =====
    init_bias(acc, be, nullptr, tx);
    pref_w(pf, Wa, 64, t);
    gemm4<false>(B2, WD0, ty, tx, acc);
    EPI_LOOP(
        B1[o * PAD + row]       = sigm(v.x);
        B1[(o + 1) * PAD + row] = sigm(v.y);
    )
    commit_w(WD1, pf, t);
    __syncthreads();

    // ===== u7: B2 @ Wa -> B3 = res  (prefetch t8 = W_ih[:, 0:64]) =====
    init_bias(acc, ba, nullptr, tx);
    pref_w(pf, W_ih, 192, t);
    gemm4<false>(B2, WD1, ty, tx, acc);
    EPI_LOOP(
        float gg = __ldg(&ea_w[c0 + row]);
        float mnx = B2[o * PAD + row];
        float sgx = B1[o * PAD + row];
        float mny = B2[(o + 1) * PAD + row];
        float sgy = B1[(o + 1) * PAD + row];
        B3[o * PAD + row]       = mnx - gg * sgx * mnx + gg * tanhf(v.x);
        B3[(o + 1) * PAD + row] = mny - gg * sgy * mny + gg * tanhf(v.y);
    )
    commit_w(WD0, pf, t);
    __syncthreads();

    // ===== u8: B3 @ W_ih_r  (prefetch t9 = W_hh[:, 0:64]) =====
    init_bias(acc, b_ih, b_hh, tx);
    pref_w(pf, W_hh, 192, t);
    gemm4<false>(B3, WD0, ty, tx, acc);
    commit_w(WD1, pf, t);
    __syncthreads();

    // ===== u9: + XH @ W_hh_r -> B1 = r  (prefetch t10 = W_ih[:, 64:128]) ===
    pref_w(pf, W_ih + 64, 192, t);
    gemm4<false>(XH, WD1, ty, tx, acc);
    EPI_LOOP(
        B1[o * PAD + row]       = sigm(v.x);
        B1[(o + 1) * PAD + row] = sigm(v.y);
    )
    commit_w(WD0, pf, t);
    __syncthreads();

    // ===== u10: B3 @ W_ih_z  (prefetch t11 = W_hh[:, 64:128]) =====
    init_bias(acc, b_ih + 64, b_hh + 64, tx);
    pref_w(pf, W_hh + 64, 192, t);
    gemm4<false>(B3, WD0, ty, tx, acc);
    commit_w(WD1, pf, t);
    __syncthreads();

    // ===== u11: + XH @ W_hh_z -> B2 = z  (prefetch t12 = W_hh[:, 128:192]) =
    pref_w(pf, W_hh + 128, 192, t);
    gemm4<false>(XH, WD1, ty, tx, acc);
    EPI_LOOP(
        B2[o * PAD + row]       = sigm(v.x);
        B2[(o + 1) * PAD + row] = sigm(v.y);
    )
    commit_w(WD0, pf, t);
    __syncthreads();

    // ===== u12: XH @ W_hh_n -> B4  (prefetch t13 = W_ih[:, 128:192]) =====
    init_bias(acc, b_hh + 128, nullptr, tx);
    pref_w(pf, W_ih + 128, 192, t);
    gemm4<false>(XH, WD0, ty, tx, acc);
    EPI_LOOP(
        B4[o * PAD + row]       = v.x;
        B4[(o + 1) * PAD + row] = v.y;
    )
    commit_w(WD1, pf, t);
    __syncthreads();

    // ===== u13: B3 @ W_ih_n -> n, h_next -> B1 =====
    init_bias(acc, b_ih + 128, nullptr, tx);
    gemm4<false>(B3, WD1, ty, tx, acc);
    EPI_LOOP(
        float hnx = B4[o * PAD + row];
        float hny = B4[(o + 1) * PAD + row];
        float rrx = B1[o * PAD + row];
        float rry = B1[(o + 1) * PAD + row];
        float zzx = B2[o * PAD + row];
        float zzy = B2[(o + 1) * PAD + row];
        float hvx = XH[o * PAD + row];
        float hvy = XH[(o + 1) * PAD + row];
        float nx = tanhf(v.x + rrx * hnx);
        float ny = tanhf(v.y + rry * hny);
        B1[o * PAD + row]       = (1.f - zzx) * nx + zzx * hvx;
        B1[(o + 1) * PAD + row] = (1.f - zzy) * ny + zzy * hvy;
    )
    __syncthreads();

    // ===== readout: y = sigm(h_next @ Wp + bp) =====
    {
        int row = t >> 1, half = t & 1;
        float s = 0.f;
        const float* hb = B1 + half * 32 * PAD + row;
#pragma unroll
        for (int o = 0; o < 32; ++o)
            s += hb[o * PAD] * __ldg(Wp + half * 32 + o);
        s += __shfl_xor_sync(0xffffffffu, s, 1);
        if (half == 0)
            out[row0 + row] = sigm(s + __ldg(bp));
    }
}

extern "C" void kernel_launch(void* const* d_in, const int* in_sizes, int n_in,
                              void* d_out, int out_size) {
    const int*   qt     = (const int*)  d_in[1];
    const float* ht     = (const float*)d_in[2];
    const float* onehot = (const float*)d_in[3];
    const float* kc     = (const float*)d_in[4];
    const float* graphs = (const float*)d_in[5];
    const float* nw     = (const float*)d_in[6];
    const float* Ws1    = (const float*)d_in[7];
    const float* bs1    = (const float*)d_in[8];
    const float* Ws2    = (const float*)d_in[9];
    const float* bs2    = (const float*)d_in[10];
    const float* Wn1    = (const float*)d_in[11];
    const float* bn1    = (const float*)d_in[12];
    const float* Wn2    = (const float*)d_in[13];
    const float* bn2    = (const float*)d_in[14];
    const float* ea_w   = (const float*)d_in[15];
    const float* We     = (const float*)d_in[16];
    const float* be     = (const float*)d_in[17];
    const float* Wa     = (const float*)d_in[18];
    const float* ba     = (const float*)d_in[19];
    const float* W_ih   = (const float*)d_in[20];
    const float* b_ih   = (const float*)d_in[21];
    const float* W_hh   = (const float*)d_in[22];
    const float* b_hh   = (const float*)d_in[23];
    const float* Wp     = (const float*)d_in[24];
    const float* bp     = (const float*)d_in[25];
    float* out = (float*)d_out;

    gkt_adj<<<1, 1024>>>(qt, onehot, graphs);

    const int smem_bytes = SM_TOT * (int)sizeof(float);   // 201728 B
    cudaFuncSetAttribute(gkt_main, cudaFuncAttributeMaxDynamicSharedMemorySize, smem_bytes);
    const int nrows = 256 * C_DIM;
    gkt_main<<<nrows / TILE_R, TPB, smem_bytes>>>(
        qt, ht, onehot, kc, nw,
        Ws1, bs1, Ws2, bs2, Wn1, bn1, Wn2, bn2,
        ea_w, We, be, Wa, ba, W_ih, b_ih, W_hh, b_hh, Wp, bp,
        out);
}